// round 15
// baseline (speedup 1.0000x reference)
#include <cuda_runtime.h>
#include <math.h>

#define BB 64
#define MM 2048
#define CC 64
#define HH 128
#define NNZE 32768
#define H3 384
#define PADN 40960

// -------- scratch (static device arrays; no runtime malloc) --------
__device__ int           g_hist[BB*MM];     // row edge counts (gmem RED)
__device__ int           g_cur[BB*MM];      // scatter cursors (gmem ATOMG)
__device__ int           g_cluscnt[BB*CC];
__device__ int           g_clusoff[BB*CC];
__device__ int           g_csplit[BB*CC*4];
__device__ unsigned char g_nit[BB*MM];
__device__ int2          g_csr[BB*PADN];
__device__ float         g_xdec[BB*CC*H3];
__device__ float         g_Q[BB*CC*HH];
__device__ float         g_K[BB*CC*HH];
__device__ float         g_V[BB*CC*HH];

// ============ K0: zero the gmem histogram ============
__global__ void k_zero() {
    int i = blockIdx.x * 256 + threadIdx.x;     // 128 blocks x 256 x int4
    ((int4*)g_hist)[i] = make_int4(0, 0, 0, 0);
}

// ============ K1a: row histogram via spread gmem atomics (2048 CTAs) =====
__global__ void __launch_bounds__(256) k_hist(const int* __restrict__ rows) {
    int i0 = blockIdx.x * 1024 + threadIdx.x;
    #pragma unroll
    for (int k = 0; k < 4; k++) {
        int i = i0 + k * 256;
        int g = i >> 15;
        atomicAdd(&g_hist[(g << 11) + __ldg(&rows[i])], 1);
    }
}

// ============ K1b: per-graph cluster ordering + padded scan + metadata ===
__global__ void __launch_bounds__(1024) k_build(const int* __restrict__ idx) {
    __shared__ short pos2row[MM];
    __shared__ int   ss[1024];
    __shared__ int   curs[MM];
    __shared__ int   chist[CC], ccur[CC], coffs[CC];
    int g = blockIdx.x, tid = threadIdx.x;
    if (tid < CC) chist[tid] = 0;
    __syncthreads();

    const int* ix = idx + g * MM;
    int i0 = __ldg(&ix[tid]), i1 = __ldg(&ix[tid + 1024]);
    atomicAdd(&chist[i0], 1);
    atomicAdd(&chist[i1], 1);
    __syncthreads();

    if (tid == 0) {
        int acc = 0;
        for (int c = 0; c < CC; c++) {
            coffs[c] = acc; ccur[c] = acc;
            g_clusoff[g*CC + c] = acc;
            g_cluscnt[g*CC + c] = chist[c];
            acc += chist[c];
        }
    }
    __syncthreads();

    int p0 = atomicAdd(&ccur[i0], 1); pos2row[p0] = (short)tid;
    int p1 = atomicAdd(&ccur[i1], 1); pos2row[p1] = (short)(tid + 1024);
    __syncthreads();

    int r0 = pos2row[2*tid], r1 = pos2row[2*tid + 1];
    int len0 = g_hist[g*MM + r0], len1 = g_hist[g*MM + r1];
    int l0 = (len0 + 3) & ~3, l1 = (len1 + 3) & ~3;
    int t = l0 + l1;
    ss[tid] = t;
    __syncthreads();
    for (int off = 1; off < 1024; off <<= 1) {
        int v = (tid >= off) ? ss[tid - off] : 0;
        __syncthreads();
        ss[tid] += v;
        __syncthreads();
    }
    int excl = ss[tid] - t;
    int o0 = excl, o1 = excl + l0;
    curs[r0] = o0;  curs[r1] = o1;
    g_cur[g*MM + r0] = o0;
    g_cur[g*MM + r1] = o1;
    g_nit[g*MM + 2*tid]     = (unsigned char)(l0 >> 2);
    g_nit[g*MM + 2*tid + 1] = (unsigned char)(l1 >> 2);

    // zero the padding slots
    int2* cbase = g_csr + (size_t)g * PADN;
    for (int k = len0; k < l0; k++) cbase[o0 + k] = make_int2(0, 0);
    for (int k = len1; k < l1; k++) cbase[o1 + k] = make_int2(0, 0);
    __syncthreads();

    if (tid < CC) {
        int cp = coffs[tid], nr = chist[tid];
        #pragma unroll
        for (int q = 0; q < 4; q++) {
            int qs = (nr * q) >> 2;
            g_csplit[(g*CC + tid)*4 + q] =
                (nr > 0) ? curs[pos2row[cp + qs]] : 0;
        }
    }
}

// ============ K1c: scatter edges via gmem atomic cursors (2048 CTAs) =====
__global__ void __launch_bounds__(256) k_scatter(const int* __restrict__ rows,
                                                 const int* __restrict__ cols,
                                                 const float* __restrict__ vals) {
    int i0 = blockIdx.x * 1024 + threadIdx.x;
    #pragma unroll
    for (int k = 0; k < 4; k++) {
        int i = i0 + k * 256;
        int g = i >> 15;
        int r = __ldg(&rows[i]);
        int c = __ldg(&cols[i]);
        float v = __ldg(&vals[i]);
        int p = atomicAdd(&g_cur[(g << 11) + r], 1);
        g_csr[(size_t)g * PADN + p] = make_int2(c, __float_as_int(v));
    }
}

// ============ K2: SpMM + pooling (round-7 fp32; at the L2 traffic floor) ==
__global__ void __launch_bounds__(256) k_spmm(const float4* __restrict__ x4) {
    __shared__ float comb[2][3][32][8];
    int g = blockIdx.x >> 5;
    int cgrp = blockIdx.x & 31;
    int wid = threadIdx.x >> 5, lane = threadIdx.x & 31;
    int ci = wid >> 2;
    int sub = wid & 3;
    int c = cgrp * 2 + ci;
    int nr  = g_cluscnt[g*CC + c];
    int pos = g_clusoff[g*CC + c];
    int lo = (nr * sub) >> 2, hi = (nr * (sub + 1)) >> 2;
    int eptr = g_csplit[(g*CC + c)*4 + sub];
    const float4* xq = x4 + (size_t)g * MM * 32;
    const int4* cs = (const int4*)(g_csr + (size_t)g * PADN + eptr);
    const unsigned char* nitp = g_nit + g * MM + pos;

    float4 s  = make_float4(0.f, 0.f, 0.f, 0.f);
    float4 mx = make_float4(-INFINITY, -INFINITY, -INFINITY, -INFINITY);

    for (int j0 = lo; j0 < hi; j0 += 32) {
        int lim = min(32, hi - j0);
        int myv = (lane < lim) ? (int)nitp[j0 + lane] : 0;
        for (int j = 0; j < lim; j++) {
            int it = __shfl_sync(0xFFFFFFFFu, myv, j);
            float4 acc = make_float4(0.f, 0.f, 0.f, 0.f);
            #pragma unroll 2
            for (int t = 0; t < it; t++) {
                int4 a = __ldg(cs);
                int4 b = __ldg(cs + 1);
                cs += 2;
                float4 v0 = __ldg(&xq[a.x * 32 + lane]);
                float4 v1 = __ldg(&xq[a.z * 32 + lane]);
                float4 v2 = __ldg(&xq[b.x * 32 + lane]);
                float4 v3 = __ldg(&xq[b.z * 32 + lane]);
                float f0 = __int_as_float(a.y), f1 = __int_as_float(a.w);
                float f2 = __int_as_float(b.y), f3 = __int_as_float(b.w);
                acc.x += f0*v0.x + f1*v1.x + f2*v2.x + f3*v3.x;
                acc.y += f0*v0.y + f1*v1.y + f2*v2.y + f3*v3.y;
                acc.z += f0*v0.z + f1*v1.z + f2*v2.z + f3*v3.z;
                acc.w += f0*v0.w + f1*v1.w + f2*v2.w + f3*v3.w;
            }
            s.x += acc.x; s.y += acc.y; s.z += acc.z; s.w += acc.w;
            mx.x = fmaxf(mx.x, acc.x); mx.y = fmaxf(mx.y, acc.y);
            mx.z = fmaxf(mx.z, acc.z); mx.w = fmaxf(mx.w, acc.w);
        }
    }
    if (sub != 0) {
        float* cb = comb[ci][sub - 1][lane];
        cb[0] = s.x;  cb[1] = s.y;  cb[2] = s.z;  cb[3] = s.w;
        cb[4] = mx.x; cb[5] = mx.y; cb[6] = mx.z; cb[7] = mx.w;
    }
    __syncthreads();
    if (sub == 0) {
        #pragma unroll
        for (int w = 0; w < 3; w++) {
            const float* cb = comb[ci][w][lane];
            s.x += cb[0]; s.y += cb[1]; s.z += cb[2]; s.w += cb[3];
            mx.x = fmaxf(mx.x, cb[4]); mx.y = fmaxf(mx.y, cb[5]);
            mx.z = fmaxf(mx.z, cb[6]); mx.w = fmaxf(mx.w, cb[7]);
        }
        float cf = fmaxf((float)nr, 1.f);
        float* xd = g_xdec + (g*CC + c) * H3;
        float4 mean = make_float4(s.x/cf, s.y/cf, s.z/cf, s.w/cf);
        *(float4*)&xd[lane*4]        = mean;
        *(float4*)&xd[HH + lane*4]   = mx;
        *(float4*)&xd[2*HH + lane*4] = s;
    }
}

// ============ packed f32x2 helpers ============
__device__ __forceinline__ void ffma2(unsigned long long& d,
                                      unsigned long long a,
                                      unsigned long long b) {
    asm("fma.rn.f32x2 %0, %1, %2, %0;" : "+l"(d) : "l"(a), "l"(b));
}
__device__ __forceinline__ unsigned long long pack2(float v) {
    unsigned long long r;
    asm("mov.b64 %0, {%1, %1};" : "=l"(r) : "f"(v));
    return r;
}

// ============ K3: Q/K/V = x_dec @ W (R8 exact config; measured 47.4us) ====
#define XS_LD 68
__global__ void __launch_bounds__(256) k_gemm(const float* __restrict__ Wq,
                                              const float* __restrict__ Wk,
                                              const float* __restrict__ Wv) {
    extern __shared__ float sm[];
    float* xsA = sm;                // [64 k][68 pad] transposed A tile
    float* ws  = sm + 64 * XS_LD;   // [64 k][64 n-half] W tile
    int g = blockIdx.x, which = blockIdx.y, zh = blockIdx.z;
    const float* W = ((which == 0) ? Wq : (which == 1) ? Wk : Wv) + zh * 64;
    float* out = ((which == 0) ? g_Q : (which == 1) ? g_K : g_V)
                 + g * CC * HH + zh * 64;
    const float* xd = g_xdec + g * CC * H3;
    int tid = threadIdx.x;
    int ty = tid >> 4, tx = tid & 15;

    unsigned long long acc[4][2];
    #pragma unroll
    for (int i = 0; i < 4; i++) { acc[i][0] = 0ull; acc[i][1] = 0ull; }

    for (int kt = 0; kt < H3; kt += 64) {
        __syncthreads();
        for (int i = tid; i < 64 * 64; i += 256) {
            int rr = i >> 6, kk = i & 63;
            xsA[kk * XS_LD + rr] = xd[rr * H3 + kt + kk];
        }
        for (int i = tid; i < 64 * 16; i += 256) {
            int row = i >> 4, cidx = i & 15;
            *(float4*)&ws[row * 64 + cidx * 4] =
                *(const float4*)&W[(kt + row) * HH + cidx * 4];
        }
        __syncthreads();
        #pragma unroll 8
        for (int kk = 0; kk < 64; kk++) {
            float4 av = *(const float4*)&xsA[kk * XS_LD + ty * 4];
            ulonglong2 b = *(const ulonglong2*)&ws[kk * 64 + tx * 4];
            unsigned long long pa0 = pack2(av.x), pa1 = pack2(av.y);
            unsigned long long pa2 = pack2(av.z), pa3 = pack2(av.w);
            ffma2(acc[0][0], pa0, b.x);  ffma2(acc[0][1], pa0, b.y);
            ffma2(acc[1][0], pa1, b.x);  ffma2(acc[1][1], pa1, b.y);
            ffma2(acc[2][0], pa2, b.x);  ffma2(acc[2][1], pa2, b.y);
            ffma2(acc[3][0], pa3, b.x);  ffma2(acc[3][1], pa3, b.y);
        }
    }
    #pragma unroll
    for (int i = 0; i < 4; i++) {
        ulonglong2 o; o.x = acc[i][0]; o.y = acc[i][1];
        *(ulonglong2*)&out[(ty*4 + i) * HH + tx * 4] = o;
    }
}

// ============ K4: attention (measured 15.4us) ============================
__global__ void __launch_bounds__(256) k_attn(float* __restrict__ out) {
    extern __shared__ float sm[];
    float* Qs = sm;                   // 16 * 132
    float* Ks = Qs + 16 * 132;        // 64 * 132
    float* Vs = Ks + 64 * 132;        // 64 * 132
    float* Ss = Vs + 64 * 132;        // 16 * 68
    int g = blockIdx.x, rh = blockIdx.y * 16, tid = threadIdx.x;
    const float4* Qg = (const float4*)(g_Q + g * CC * HH + rh * HH);
    const float4* Kg = (const float4*)(g_K + g * CC * HH);
    const float4* Vg = (const float4*)(g_V + g * CC * HH);

    for (int i = tid; i < 16 * 32; i += 256) {
        int r = i >> 5, cc = i & 31;
        ((float4*)Qs)[r * 33 + cc] = __ldg(&Qg[r * 32 + cc]);
    }
    for (int i = tid; i < 64 * 32; i += 256) {
        int r = i >> 5, cc = i & 31;
        ((float4*)Ks)[r * 33 + cc] = __ldg(&Kg[r * 32 + cc]);
        ((float4*)Vs)[r * 33 + cc] = __ldg(&Vg[r * 32 + cc]);
    }
    __syncthreads();

    int r = tid & 15, grp = tid >> 4;      // 16 rows x 16 col-groups
    {
        float sacc[4] = {0.f, 0.f, 0.f, 0.f};
        const float4* q4 = (const float4*)Qs + r * 33;
        const float4* k4 = (const float4*)Ks;
        #pragma unroll 4
        for (int h4 = 0; h4 < 32; h4++) {
            float4 q = q4[h4];
            #pragma unroll
            for (int cc = 0; cc < 4; cc++) {
                float4 k = k4[(grp*4 + cc) * 33 + h4];
                sacc[cc] += q.x*k.x + q.y*k.y + q.z*k.z + q.w*k.w;
            }
        }
        const float scale = 0.08838834764831845f;   // 1/sqrt(128)
        #pragma unroll
        for (int cc = 0; cc < 4; cc++) Ss[r*68 + grp*4 + cc] = sacc[cc] * scale;
    }
    __syncthreads();
    // warp-parallel softmax: 8 warps x 2 rows; 16 lanes per row, 4 cols/lane
    {
        int wid = tid >> 5, lane = tid & 31;
        int rr = wid * 2 + (lane >> 4);
        int l16 = lane & 15;
        float v0 = Ss[rr*68 + l16];
        float v1 = Ss[rr*68 + l16 + 16];
        float v2 = Ss[rr*68 + l16 + 32];
        float v3 = Ss[rr*68 + l16 + 48];
        float m = fmaxf(fmaxf(v0, v1), fmaxf(v2, v3));
        #pragma unroll
        for (int o = 1; o < 16; o <<= 1)
            m = fmaxf(m, __shfl_xor_sync(0xFFFFFFFFu, m, o));
        float e0 = __expf(v0 - m), e1 = __expf(v1 - m);
        float e2 = __expf(v2 - m), e3 = __expf(v3 - m);
        float sum = e0 + e1 + e2 + e3;
        #pragma unroll
        for (int o = 1; o < 16; o <<= 1)
            sum += __shfl_xor_sync(0xFFFFFFFFu, sum, o);
        float inv = 1.f / sum;
        Ss[rr*68 + l16]      = e0 * inv;
        Ss[rr*68 + l16 + 16] = e1 * inv;
        Ss[rr*68 + l16 + 32] = e2 * inv;
        Ss[rr*68 + l16 + 48] = e3 * inv;
    }
    __syncthreads();
    {
        float4 a0 = make_float4(0.f,0.f,0.f,0.f), a1 = a0;
        const float4* v4 = (const float4*)Vs;
        #pragma unroll 4
        for (int c = 0; c < CC; c++) {
            float p = Ss[r*68 + c];
            float4 v0 = v4[c * 33 + grp * 2];
            float4 v1 = v4[c * 33 + grp * 2 + 1];
            a0.x += p*v0.x; a0.y += p*v0.y; a0.z += p*v0.z; a0.w += p*v0.w;
            a1.x += p*v1.x; a1.y += p*v1.y; a1.z += p*v1.z; a1.w += p*v1.w;
        }
        float4* o4 = (float4*)out + g * 2048 + (rh + r) * 32 + grp * 2;
        o4[0] = a0; o4[1] = a1;
    }
}

extern "C" void kernel_launch(void* const* d_in, const int* in_sizes, int n_in,
                              void* d_out, int out_size) {
    const float* x    = (const float*)d_in[0];
    const int*   rows = (const int*)d_in[3];
    const int*   cols = (const int*)d_in[4];
    const float* vals = (const float*)d_in[5];
    const int*   idx  = (const int*)d_in[6];
    const float* Wq   = (const float*)d_in[7];
    const float* Wk   = (const float*)d_in[8];
    const float* Wv   = (const float*)d_in[9];
    float* out = (float*)d_out;

    static const int GEMM_SMEM = (64*XS_LD + 64*64) * 4;            // 33792 B
    static const int ATTN_SMEM = ((16 + 2*64) * 132 + 16*68) * 4;   // 80384 B
    cudaFuncSetAttribute(k_gemm, cudaFuncAttributeMaxDynamicSharedMemorySize, GEMM_SMEM);
    cudaFuncSetAttribute(k_attn, cudaFuncAttributeMaxDynamicSharedMemorySize, ATTN_SMEM);

    k_zero<<<128, 256>>>();
    k_hist<<<2048, 256>>>(rows);
    k_build<<<BB, 1024>>>(idx);
    k_scatter<<<2048, 256>>>(rows, cols, vals);
    k_spmm<<<BB * 32, 256>>>((const float4*)x);
    k_gemm<<<dim3(BB, 3, 2), 256, GEMM_SMEM>>>(Wq, Wk, Wv);
    k_attn<<<dim3(BB, 4), 256, ATTN_SMEM>>>(out);
}

// round 16
// speedup vs baseline: 1.1657x; 1.1657x over previous
#include <cuda_runtime.h>
#include <math.h>

#define BB 64
#define MM 2048
#define CC 64
#define HH 128
#define NNZE 32768
#define H3 384
#define PADN 40960

// -------- scratch (static device arrays; no runtime malloc) --------
__device__ int           g_cluscnt[BB*CC];
__device__ int           g_clusoff[BB*CC];
__device__ int           g_csplit[BB*CC*4];
__device__ unsigned char g_nit[BB*MM];
__device__ int2          g_csr[BB*PADN];
__device__ float         g_xdec[BB*CC*H3];
__device__ float         g_qkv2[2][3][BB*CC*HH];  // [K-half][Q/K/V]

// ============ K1: build cluster-ordered padded CSR (R7; measured 36.3us) ==
__global__ void __launch_bounds__(1024) k_prep(const int* __restrict__ rows,
                                               const int* __restrict__ cols,
                                               const float* __restrict__ vals,
                                               const int* __restrict__ idx) {
    __shared__ int   hist[MM];
    __shared__ int   cur[MM];
    __shared__ int   ss[1024];
    __shared__ short pos2row[MM];
    __shared__ int   chist[CC], ccur[CC], coffs[CC];
    int g = blockIdx.x, tid = threadIdx.x;
    hist[tid] = 0; hist[tid + 1024] = 0;
    if (tid < CC) chist[tid] = 0;
    __syncthreads();

    const int* r  = rows + g * NNZE;
    const int* ix = idx  + g * MM;
    for (int i = tid; i < NNZE; i += 1024) atomicAdd(&hist[r[i]], 1);
    int i0 = ix[tid], i1 = ix[tid + 1024];
    atomicAdd(&chist[i0], 1);
    atomicAdd(&chist[i1], 1);
    __syncthreads();

    if (tid == 0) {
        int acc = 0;
        for (int c = 0; c < CC; c++) {
            coffs[c] = acc; ccur[c] = acc;
            g_clusoff[g*CC + c] = acc;
            g_cluscnt[g*CC + c] = chist[c];
            acc += chist[c];
        }
    }
    __syncthreads();

    int p0 = atomicAdd(&ccur[i0], 1); pos2row[p0] = (short)tid;
    int p1 = atomicAdd(&ccur[i1], 1); pos2row[p1] = (short)(tid + 1024);
    __syncthreads();

    int r0 = pos2row[2*tid], r1 = pos2row[2*tid + 1];
    int len0 = hist[r0], len1 = hist[r1];
    int l0 = (len0 + 3) & ~3, l1 = (len1 + 3) & ~3;
    int t = l0 + l1;
    ss[tid] = t;
    __syncthreads();
    for (int off = 1; off < 1024; off <<= 1) {
        int v = (tid >= off) ? ss[tid - off] : 0;
        __syncthreads();
        ss[tid] += v;
        __syncthreads();
    }
    int excl = ss[tid] - t;
    int o0 = excl, o1 = excl + l0;
    cur[r0] = o0;  cur[r1] = o1;
    g_nit[g*MM + 2*tid]     = (unsigned char)(l0 >> 2);
    g_nit[g*MM + 2*tid + 1] = (unsigned char)(l1 >> 2);

    int2* cbase = g_csr + (size_t)g * PADN;
    for (int k = len0; k < l0; k++) cbase[o0 + k] = make_int2(0, 0);
    for (int k = len1; k < l1; k++) cbase[o1 + k] = make_int2(0, 0);
    __syncthreads();

    if (tid < CC) {
        int cp = coffs[tid], nr = chist[tid];
        #pragma unroll
        for (int q = 0; q < 4; q++) {
            int qs = (nr * q) >> 2;
            g_csplit[(g*CC + tid)*4 + q] =
                (nr > 0) ? cur[pos2row[cp + qs]] : 0;
        }
    }
    __syncthreads();

    const int*   c = cols + g * NNZE;
    const float* v = vals + g * NNZE;
    for (int i = tid; i < NNZE; i += 1024) {
        int rr = r[i];
        int p = atomicAdd(&cur[rr], 1);
        cbase[p] = make_int2(c[i], __float_as_int(v[i]));
    }
}

// ============ K2: SpMM + pooling (R7; at the L2 traffic floor) ===========
__global__ void __launch_bounds__(256) k_spmm(const float4* __restrict__ x4) {
    __shared__ float comb[2][3][32][8];
    int g = blockIdx.x >> 5;
    int cgrp = blockIdx.x & 31;
    int wid = threadIdx.x >> 5, lane = threadIdx.x & 31;
    int ci = wid >> 2;
    int sub = wid & 3;
    int c = cgrp * 2 + ci;
    int nr  = g_cluscnt[g*CC + c];
    int pos = g_clusoff[g*CC + c];
    int lo = (nr * sub) >> 2, hi = (nr * (sub + 1)) >> 2;
    int eptr = g_csplit[(g*CC + c)*4 + sub];
    const float4* xq = x4 + (size_t)g * MM * 32;
    const int4* cs = (const int4*)(g_csr + (size_t)g * PADN + eptr);
    const unsigned char* nitp = g_nit + g * MM + pos;

    float4 s  = make_float4(0.f, 0.f, 0.f, 0.f);
    float4 mx = make_float4(-INFINITY, -INFINITY, -INFINITY, -INFINITY);

    for (int j0 = lo; j0 < hi; j0 += 32) {
        int lim = min(32, hi - j0);
        int myv = (lane < lim) ? (int)nitp[j0 + lane] : 0;
        for (int j = 0; j < lim; j++) {
            int it = __shfl_sync(0xFFFFFFFFu, myv, j);
            float4 acc = make_float4(0.f, 0.f, 0.f, 0.f);
            #pragma unroll 2
            for (int t = 0; t < it; t++) {
                int4 a = __ldg(cs);
                int4 b = __ldg(cs + 1);
                cs += 2;
                float4 v0 = __ldg(&xq[a.x * 32 + lane]);
                float4 v1 = __ldg(&xq[a.z * 32 + lane]);
                float4 v2 = __ldg(&xq[b.x * 32 + lane]);
                float4 v3 = __ldg(&xq[b.z * 32 + lane]);
                float f0 = __int_as_float(a.y), f1 = __int_as_float(a.w);
                float f2 = __int_as_float(b.y), f3 = __int_as_float(b.w);
                acc.x += f0*v0.x + f1*v1.x + f2*v2.x + f3*v3.x;
                acc.y += f0*v0.y + f1*v1.y + f2*v2.y + f3*v3.y;
                acc.z += f0*v0.z + f1*v1.z + f2*v2.z + f3*v3.z;
                acc.w += f0*v0.w + f1*v1.w + f2*v2.w + f3*v3.w;
            }
            s.x += acc.x; s.y += acc.y; s.z += acc.z; s.w += acc.w;
            mx.x = fmaxf(mx.x, acc.x); mx.y = fmaxf(mx.y, acc.y);
            mx.z = fmaxf(mx.z, acc.z); mx.w = fmaxf(mx.w, acc.w);
        }
    }
    if (sub != 0) {
        float* cb = comb[ci][sub - 1][lane];
        cb[0] = s.x;  cb[1] = s.y;  cb[2] = s.z;  cb[3] = s.w;
        cb[4] = mx.x; cb[5] = mx.y; cb[6] = mx.z; cb[7] = mx.w;
    }
    __syncthreads();
    if (sub == 0) {
        #pragma unroll
        for (int w = 0; w < 3; w++) {
            const float* cb = comb[ci][w][lane];
            s.x += cb[0]; s.y += cb[1]; s.z += cb[2]; s.w += cb[3];
            mx.x = fmaxf(mx.x, cb[4]); mx.y = fmaxf(mx.y, cb[5]);
            mx.z = fmaxf(mx.z, cb[6]); mx.w = fmaxf(mx.w, cb[7]);
        }
        float cf = fmaxf((float)nr, 1.f);
        float* xd = g_xdec + (g*CC + c) * H3;
        float4 mean = make_float4(s.x/cf, s.y/cf, s.z/cf, s.w/cf);
        *(float4*)&xd[lane*4]        = mean;
        *(float4*)&xd[HH + lane*4]   = mx;
        *(float4*)&xd[2*HH + lane*4] = s;
    }
}

// ============ packed f32x2 helpers ============
__device__ __forceinline__ void ffma2(unsigned long long& d,
                                      unsigned long long a,
                                      unsigned long long b) {
    asm("fma.rn.f32x2 %0, %1, %2, %0;" : "+l"(d) : "l"(a), "l"(b));
}
__device__ __forceinline__ unsigned long long pack2(float v) {
    unsigned long long r;
    asm("mov.b64 %0, {%1, %1};" : "=l"(r) : "f"(v));
    return r;
}

// ============ K3: Q/K/V GEMM, 8x8 microtile, grid (64,3,2 K-halves) ======
// Mechanism fix for R8's measured L1=60% (smem-BW bound): B-bytes per
// FFMA2 halved (32B per 32 FFMA2), A reads are 16-lane scalar broadcasts.
// 128 threads = 8 row-groups x 16 col-groups; 384 CTAs. Partials per
// K-half land in g_qkv2; k_attn sums them during staging (R12: +0.6us).
#define XS_LD 68
__global__ void __launch_bounds__(128) k_gemm(const float* __restrict__ Wq,
                                              const float* __restrict__ Wk,
                                              const float* __restrict__ Wv) {
    extern __shared__ float sm[];
    float* xsA = sm;                // [64 row][68 pad] A tile (row-major)
    float* Bs  = sm + 64 * XS_LD;   // [64 kk][128 col] W tile
    int g = blockIdx.x, which = blockIdx.y, kh = blockIdx.z;
    const float* W = (which == 0) ? Wq : (which == 1) ? Wk : Wv;
    float* out = g_qkv2[kh][which] + g * CC * HH;
    const float* xd = g_xdec + g * CC * H3 + kh * 192;
    int tid = threadIdx.x;
    int ty = tid >> 4, tx = tid & 15;   // rows ty*8..+7, cols tx*8..+7

    unsigned long long acc[8][4];
    #pragma unroll
    for (int i = 0; i < 8; i++)
        #pragma unroll
        for (int j = 0; j < 4; j++) acc[i][j] = 0ull;

    for (int kt = 0; kt < 192; kt += 64) {
        __syncthreads();
        // A tile: float4 coalesced LDG, conflict-free float4 STS
        for (int i = tid; i < 64 * 16; i += 128) {
            int rr = i >> 4, k4 = i & 15;
            *(float4*)&xsA[rr * XS_LD + k4 * 4] =
                __ldg((const float4*)&xd[rr * H3 + kt + k4 * 4]);
        }
        // B tile [64 kk][128 col]
        for (int i = tid; i < 64 * 32; i += 128) {
            int row = i >> 5, c4 = i & 31;
            *(float4*)&Bs[row * HH + c4 * 4] =
                __ldg((const float4*)&W[(kh * 192 + kt + row) * HH + c4 * 4]);
        }
        __syncthreads();
        #pragma unroll 4
        for (int kk = 0; kk < 64; kk++) {
            unsigned long long pa[8];
            #pragma unroll
            for (int rr = 0; rr < 8; rr++)
                pa[rr] = pack2(xsA[(ty * 8 + rr) * XS_LD + kk]);  // broadcast
            const float* wb = &Bs[kk * HH + tx * 8];
            ulonglong2 b01 = *(const ulonglong2*)wb;
            ulonglong2 b23 = *(const ulonglong2*)(wb + 4);
            #pragma unroll
            for (int rr = 0; rr < 8; rr++) {
                ffma2(acc[rr][0], pa[rr], b01.x);
                ffma2(acc[rr][1], pa[rr], b01.y);
                ffma2(acc[rr][2], pa[rr], b23.x);
                ffma2(acc[rr][3], pa[rr], b23.y);
            }
        }
    }
    #pragma unroll
    for (int i = 0; i < 8; i++) {
        ulonglong2 o0; o0.x = acc[i][0]; o0.y = acc[i][1];
        ulonglong2 o1; o1.x = acc[i][2]; o1.y = acc[i][3];
        float* orow = &out[(ty * 8 + i) * HH + tx * 8];
        *(ulonglong2*)orow       = o0;
        *(ulonglong2*)(orow + 4) = o1;
    }
}

// ============ K4: attention; staging sums the two K-half partials ========
__global__ void __launch_bounds__(256) k_attn(float* __restrict__ out) {
    extern __shared__ float sm[];
    float* Qs = sm;                   // 16 * 132
    float* Ks = Qs + 16 * 132;        // 64 * 132
    float* Vs = Ks + 64 * 132;        // 64 * 132
    float* Ss = Vs + 64 * 132;        // 16 * 68
    int g = blockIdx.x, rh = blockIdx.y * 16, tid = threadIdx.x;
    const float4* Qg0 = (const float4*)(g_qkv2[0][0] + g * CC * HH + rh * HH);
    const float4* Qg1 = (const float4*)(g_qkv2[1][0] + g * CC * HH + rh * HH);
    const float4* Kg0 = (const float4*)(g_qkv2[0][1] + g * CC * HH);
    const float4* Kg1 = (const float4*)(g_qkv2[1][1] + g * CC * HH);
    const float4* Vg0 = (const float4*)(g_qkv2[0][2] + g * CC * HH);
    const float4* Vg1 = (const float4*)(g_qkv2[1][2] + g * CC * HH);

    for (int i = tid; i < 16 * 32; i += 256) {
        int r = i >> 5, cc = i & 31;
        float4 a = __ldg(&Qg0[r * 32 + cc]);
        float4 b = __ldg(&Qg1[r * 32 + cc]);
        ((float4*)Qs)[r * 33 + cc] =
            make_float4(a.x+b.x, a.y+b.y, a.z+b.z, a.w+b.w);
    }
    for (int i = tid; i < 64 * 32; i += 256) {
        int r = i >> 5, cc = i & 31;
        float4 a = __ldg(&Kg0[r * 32 + cc]);
        float4 b = __ldg(&Kg1[r * 32 + cc]);
        ((float4*)Ks)[r * 33 + cc] =
            make_float4(a.x+b.x, a.y+b.y, a.z+b.z, a.w+b.w);
        float4 c = __ldg(&Vg0[r * 32 + cc]);
        float4 d = __ldg(&Vg1[r * 32 + cc]);
        ((float4*)Vs)[r * 33 + cc] =
            make_float4(c.x+d.x, c.y+d.y, c.z+d.z, c.w+d.w);
    }
    __syncthreads();

    int r = tid & 15, grp = tid >> 4;
    {
        float sacc[4] = {0.f, 0.f, 0.f, 0.f};
        const float4* q4 = (const float4*)Qs + r * 33;
        const float4* k4 = (const float4*)Ks;
        #pragma unroll 4
        for (int h4 = 0; h4 < 32; h4++) {
            float4 q = q4[h4];
            #pragma unroll
            for (int cc = 0; cc < 4; cc++) {
                float4 k = k4[(grp*4 + cc) * 33 + h4];
                sacc[cc] += q.x*k.x + q.y*k.y + q.z*k.z + q.w*k.w;
            }
        }
        const float scale = 0.08838834764831845f;   // 1/sqrt(128)
        #pragma unroll
        for (int cc = 0; cc < 4; cc++) Ss[r*68 + grp*4 + cc] = sacc[cc] * scale;
    }
    __syncthreads();
    {
        int wid = tid >> 5, lane = tid & 31;
        int rr = wid * 2 + (lane >> 4);
        int l16 = lane & 15;
        float v0 = Ss[rr*68 + l16];
        float v1 = Ss[rr*68 + l16 + 16];
        float v2 = Ss[rr*68 + l16 + 32];
        float v3 = Ss[rr*68 + l16 + 48];
        float m = fmaxf(fmaxf(v0, v1), fmaxf(v2, v3));
        #pragma unroll
        for (int o = 1; o < 16; o <<= 1)
            m = fmaxf(m, __shfl_xor_sync(0xFFFFFFFFu, m, o));
        float e0 = __expf(v0 - m), e1 = __expf(v1 - m);
        float e2 = __expf(v2 - m), e3 = __expf(v3 - m);
        float sum = e0 + e1 + e2 + e3;
        #pragma unroll
        for (int o = 1; o < 16; o <<= 1)
            sum += __shfl_xor_sync(0xFFFFFFFFu, sum, o);
        float inv = 1.f / sum;
        Ss[rr*68 + l16]      = e0 * inv;
        Ss[rr*68 + l16 + 16] = e1 * inv;
        Ss[rr*68 + l16 + 32] = e2 * inv;
        Ss[rr*68 + l16 + 48] = e3 * inv;
    }
    __syncthreads();
    {
        float4 a0 = make_float4(0.f,0.f,0.f,0.f), a1 = a0;
        const float4* v4 = (const float4*)Vs;
        #pragma unroll 4
        for (int c = 0; c < CC; c++) {
            float p = Ss[r*68 + c];
            float4 v0 = v4[c * 33 + grp * 2];
            float4 v1 = v4[c * 33 + grp * 2 + 1];
            a0.x += p*v0.x; a0.y += p*v0.y; a0.z += p*v0.z; a0.w += p*v0.w;
            a1.x += p*v1.x; a1.y += p*v1.y; a1.z += p*v1.z; a1.w += p*v1.w;
        }
        float4* o4 = (float4*)out + g * 2048 + (rh + r) * 32 + grp * 2;
        o4[0] = a0; o4[1] = a1;
    }
}

extern "C" void kernel_launch(void* const* d_in, const int* in_sizes, int n_in,
                              void* d_out, int out_size) {
    const float* x    = (const float*)d_in[0];
    const int*   rows = (const int*)d_in[3];
    const int*   cols = (const int*)d_in[4];
    const float* vals = (const float*)d_in[5];
    const int*   idx  = (const int*)d_in[6];
    const float* Wq   = (const float*)d_in[7];
    const float* Wk   = (const float*)d_in[8];
    const float* Wv   = (const float*)d_in[9];
    float* out = (float*)d_out;

    static const int GEMM_SMEM = (64*XS_LD + 64*HH) * 4;            // 50176 B
    static const int ATTN_SMEM = ((16 + 2*64) * 132 + 16*68) * 4;   // 80384 B
    cudaFuncSetAttribute(k_gemm, cudaFuncAttributeMaxDynamicSharedMemorySize, GEMM_SMEM);
    cudaFuncSetAttribute(k_attn, cudaFuncAttributeMaxDynamicSharedMemorySize, ATTN_SMEM);

    k_prep<<<BB, 1024>>>(rows, cols, vals, idx);
    k_spmm<<<BB * 32, 256>>>((const float4*)x);
    k_gemm<<<dim3(BB, 3, 2), 128, GEMM_SMEM>>>(Wq, Wk, Wv);
    k_attn<<<dim3(BB, 4), 256, ATTN_SMEM>>>(out);
}